// round 3
// baseline (speedup 1.0000x reference)
#include <cuda_runtime.h>
#include <math.h>
#include <stdint.h>

#define BSZ 16
#define NA  8400
#define NM  64
#define NC  80
#define KTOP 10
#define EPS9 1e-9f
#define THREADS 256

// ---------------- scratch (__device__ globals; allowed) ----------------
__device__ int      g_cnt[BSZ * NA];      // #gts selecting this anchor via topk&inside
__device__ int      g_m[BSZ * NA];        // selecting gt (valid when cnt==1)
__device__ float    g_al[BSZ * NA];       // align at selection (valid when cnt==1)
__device__ float    g_ov[BSZ * NA];       // overlap at selection (valid when cnt==1)
__device__ int      g_tgt[BSZ * NA];      // final assigned gt
__device__ int      g_fg[BSZ * NA];       // final fg flag
__device__ float    g_fin[BSZ * NA];      // final align value
__device__ unsigned g_pos_al[BSZ * NM];   // per-gt max align (float bits, >=0)
__device__ unsigned g_pos_ov[BSZ * NM];   // per-gt max overlap (float bits, >=0)

// ---------------- helpers ----------------
static __device__ __forceinline__ float ciou_f(float4 g, float4 p) {
    const float eps = 1e-7f;
    float w1 = g.z - g.x, h1 = g.w - g.y;
    float w2 = p.z - p.x, h2 = p.w - p.y;
    float iw = fmaxf(fminf(g.z, p.z) - fmaxf(g.x, p.x), 0.0f);
    float ih = fmaxf(fminf(g.w, p.w) - fmaxf(g.y, p.y), 0.0f);
    float inter = iw * ih;
    float uni = w1 * h1 + w2 * h2 - inter + eps;
    float iou = inter / uni;
    float cw = fmaxf(g.z, p.z) - fminf(g.x, p.x);
    float ch = fmaxf(g.w, p.w) - fminf(g.y, p.y);
    float c2 = cw * cw + ch * ch + eps;
    float dx = p.x + p.z - g.x - g.z;
    float dy = p.y + p.w - g.y - g.w;
    float rho2 = (dx * dx + dy * dy) * 0.25f;
    float d = atanf(w1 / (h1 + eps)) - atanf(w2 / (h2 + eps));
    float v = 0.4052847345693511f * d * d;   // 4/pi^2
    float alpha = v / (v - iou + 1.0f + eps);
    return iou - (rho2 / c2 + v * alpha);
}

static __device__ __forceinline__ bool inside_box(float2 a, float4 g) {
    return (a.x - g.x > EPS9) && (a.y - g.y > EPS9) &&
           (g.z - a.x > EPS9) && (g.w - a.y > EPS9);
}

// ---------------- K0: init scratch ----------------
__global__ void k_init() {
    int i = blockIdx.x * blockDim.x + threadIdx.x;
    if (i < BSZ * NA) g_cnt[i] = 0;
    if (i < BSZ * NM) { g_pos_al[i] = 0u; g_pos_ov[i] = 0u; }
}

// ---------------- K1: per (b,m) top-10 of align, record selections --------
__global__ void __launch_bounds__(THREADS) k_phaseA(
    const float* __restrict__ pd_scores, const float* __restrict__ pd_bboxes,
    const float* __restrict__ anc, const int* __restrict__ gt_labels,
    const float* __restrict__ gt_bboxes)
{
    int bm = blockIdx.x;
    int b = bm / NM;
    int tid = threadIdx.x;

    float4 g = __ldg((const float4*)(gt_bboxes) + bm);
    int lbl = __ldg(gt_labels + bm);
    const float* sc = pd_scores + (size_t)b * NA * NC + lbl;
    const float4* pb = (const float4*)pd_bboxes + (size_t)b * NA;
    const float2* ap = (const float2*)anc;

    // per-thread sorted top-10 (value desc, index asc)
    float tv[KTOP]; int ti[KTOP];
#pragma unroll
    for (int k = 0; k < KTOP; k++) { tv[k] = -1.0f; ti[k] = 0x7fffffff; }

    for (int a = tid; a < NA; a += THREADS) {
        float2 an = __ldg(ap + a);
        float v = 0.0f;
        if (inside_box(an, g)) {
            float4 p = __ldg(pb + a);
            float ov = fmaxf(ciou_f(g, p), 0.0f);
            if (ov > 0.0f) {
                float s = __ldg(sc + (size_t)a * NC);
                float o2 = ov * ov;
                v = sqrtf(s) * o2 * o2 * o2;
            }
        }
        // within a thread, indices ascend -> equal values never displace
        if (v > tv[KTOP - 1]) {
            int j = KTOP - 1;
            while (j > 0 && v > tv[j - 1]) { tv[j] = tv[j - 1]; ti[j] = ti[j - 1]; j--; }
            tv[j] = v; ti[j] = a;
        }
    }

    __shared__ float sv[THREADS * KTOP];
    __shared__ int   si[THREADS * KTOP];
#pragma unroll
    for (int k = 0; k < KTOP; k++) { sv[tid * KTOP + k] = tv[k]; si[tid * KTOP + k] = ti[k]; }

    for (int off = THREADS / 2; off > 0; off >>= 1) {
        __syncthreads();
        if (tid < off) {
            float* va = &sv[tid * KTOP];          int* ia = &si[tid * KTOP];
            float* vb = &sv[(tid + off) * KTOP];  int* ib = &si[(tid + off) * KTOP];
            float mv[KTOP]; int mi[KTOP];
            int x = 0, y = 0;
#pragma unroll
            for (int k = 0; k < KTOP; k++) {
                bool tA = (va[x] > vb[y]) || (va[x] == vb[y] && ia[x] < ib[y]);
                if (tA) { mv[k] = va[x]; mi[k] = ia[x]; x++; }
                else    { mv[k] = vb[y]; mi[k] = ib[y]; y++; }
            }
#pragma unroll
            for (int k = 0; k < KTOP; k++) { va[k] = mv[k]; ia[k] = mi[k]; }
        }
    }
    __syncthreads();

    // top-10 winners: count only those inside the gt (mask_pos = topk & in_gts)
    if (tid < KTOP) {
        int a = si[tid];
        float al = sv[tid];
        float2 an = __ldg(ap + a);
        if (inside_box(an, g)) {
            size_t i = (size_t)b * NA + a;
            atomicAdd(&g_cnt[i], 1);
            g_m[i] = bm % NM;
            float4 p = __ldg(pb + a);
            float ov = fmaxf(ciou_f(g, p), 0.0f);
            g_al[i] = al;
            g_ov[i] = ov;
        }
    }
}

// ---------------- K2: resolve per-anchor assignment, write 4 outputs ------
__global__ void __launch_bounds__(THREADS) k_phaseB(
    const float* __restrict__ pd_scores, const float* __restrict__ pd_bboxes,
    const float* __restrict__ anc, const int* __restrict__ gt_labels,
    const float* __restrict__ gt_bboxes, float* __restrict__ out)
{
    int b = blockIdx.y;
    __shared__ float4 sg[NM];
    __shared__ int sl[NM];
    int tid = threadIdx.x;
    if (tid < NM) {
        sg[tid] = ((const float4*)gt_bboxes)[b * NM + tid];
        sl[tid] = gt_labels[b * NM + tid];
    }
    __syncthreads();

    int a = blockIdx.x * THREADS + tid;
    if (a >= NA) return;
    size_t i = (size_t)b * NA + a;

    int cnt = g_cnt[i];
    int tgt = 0; float al = 0.0f, ov = 0.0f; int fg = 0;

    if (cnt == 1) {
        tgt = g_m[i]; al = g_al[i]; ov = g_ov[i]; fg = 1;
    } else if (cnt > 1) {
        // multi-assigned: argmax over m of overlaps (ties -> lowest m)
        float2 an = ((const float2*)anc)[a];
        float4 p = ((const float4*)pd_bboxes)[(size_t)b * NA + a];
        float best = -1.0f; int bm = 0;
#pragma unroll 4
        for (int m = 0; m < NM; m++) {
            float4 g = sg[m];
            float ovm = inside_box(an, g) ? fmaxf(ciou_f(g, p), 0.0f) : 0.0f;
            if (ovm > best) { best = ovm; bm = m; }
        }
        tgt = bm; ov = best; fg = 1;
        float4 g = sg[tgt];
        if (inside_box(an, g) && ov > 0.0f) {
            float s = pd_scores[(size_t)b * NA * NC + (size_t)a * NC + sl[tgt]];
            float o2 = ov * ov;
            al = sqrtf(s) * o2 * o2 * o2;
        } else {
            al = 0.0f;
        }
    }

    g_tgt[i] = tgt; g_fg[i] = fg; g_fin[i] = al;
    if (fg) {
        atomicMax(&g_pos_al[b * NM + tgt], __float_as_uint(al));
        atomicMax(&g_pos_ov[b * NM + tgt], __float_as_uint(ov));
    }

    // outputs: [labels | bboxes | scores | fg | gt_idx], all float32
    const size_t N = (size_t)BSZ * NA;
    float* out_lab = out;
    float* out_box = out + N;
    float* out_fg  = out + N * (size_t)(1 + 4 + NC);
    float* out_idx = out_fg + N;

    out_lab[i] = fg ? (float)sl[tgt] : (float)NC;
    ((float4*)out_box)[i] = sg[tgt];
    out_fg[i]  = fg ? 1.0f : 0.0f;
    out_idx[i] = (float)tgt;
}

// ---------------- K3: norm + one-hot target_scores ----------------
__global__ void __launch_bounds__(THREADS) k_phaseD(
    const int* __restrict__ gt_labels, float* __restrict__ out)
{
    int b = blockIdx.y;
    int a = blockIdx.x * THREADS + threadIdx.x;
    if (a >= NA) return;
    size_t i = (size_t)b * NA + a;

    int fg = g_fg[i];
    float norm = 0.0f;
    int lbl = -1;
    if (fg) {
        int t = g_tgt[i];
        lbl = gt_labels[b * NM + t];
        float pa = __uint_as_float(g_pos_al[b * NM + t]);
        float po = __uint_as_float(g_pos_ov[b * NM + t]);
        norm = g_fin[i] * po / (pa + EPS9);
    }

    float4* row = (float4*)(out + (size_t)BSZ * NA * 5 + i * (size_t)NC);
    int g4 = lbl >> 2, l4 = lbl & 3;
#pragma unroll
    for (int k = 0; k < NC / 4; k++) {
        float4 w = make_float4(0.f, 0.f, 0.f, 0.f);
        if (fg && k == g4) {
            if (l4 == 0) w.x = norm;
            else if (l4 == 1) w.y = norm;
            else if (l4 == 2) w.z = norm;
            else w.w = norm;
        }
        row[k] = w;
    }
}

// ---------------- launcher ----------------
extern "C" void kernel_launch(void* const* d_in, const int* in_sizes, int n_in,
                              void* d_out, int out_size)
{
    const float* pd_scores = (const float*)d_in[0];   // (16,8400,80) f32
    const float* pd_bboxes = (const float*)d_in[1];   // (16,8400,4)  f32
    const float* anc       = (const float*)d_in[2];   // (8400,2)     f32
    const int*   gt_labels = (const int*)  d_in[3];   // (16,64,1)    i32
    const float* gt_bboxes = (const float*)d_in[4];   // (16,64,4)    f32
    // d_in[5] = mask_gt (all true) -> ignored
    float* out = (float*)d_out;

    (void)in_sizes; (void)n_in; (void)out_size;

    dim3 gInit((BSZ * NA + THREADS - 1) / THREADS);
    k_init<<<gInit, THREADS>>>();

    k_phaseA<<<BSZ * NM, THREADS>>>(pd_scores, pd_bboxes, anc, gt_labels, gt_bboxes);

    dim3 gBA((NA + THREADS - 1) / THREADS, BSZ);
    k_phaseB<<<gBA, THREADS>>>(pd_scores, pd_bboxes, anc, gt_labels, gt_bboxes, out);

    k_phaseD<<<gBA, THREADS>>>(gt_labels, out);
}

// round 4
// speedup vs baseline: 1.8662x; 1.8662x over previous
#include <cuda_runtime.h>
#include <math.h>
#include <stdint.h>

#define BSZ 16
#define NA  8400
#define NM  64
#define NC  80
#define KTOP 10
#define EPS9 1e-9f
#define THREADS 256

// ---------------- scratch (__device__ globals; allowed) ----------------
__device__ int      g_cnt[BSZ * NA];      // #gts selecting this anchor via topk&inside
__device__ int      g_m[BSZ * NA];        // selecting gt (valid when cnt==1)
__device__ float    g_al[BSZ * NA];       // align at selection (valid when cnt==1)
__device__ float    g_ov[BSZ * NA];       // overlap at selection (valid when cnt==1)
__device__ int      g_tgt[BSZ * NA];      // final assigned gt
__device__ int      g_fg[BSZ * NA];       // final fg flag
__device__ float    g_fin[BSZ * NA];      // final align value
__device__ unsigned g_pos_al[BSZ * NM];   // per-gt max align (float bits, >=0)
__device__ unsigned g_pos_ov[BSZ * NM];   // per-gt max overlap (float bits, >=0)

// ---------------- helpers ----------------
static __device__ __forceinline__ float ciou_f(float4 g, float4 p) {
    const float eps = 1e-7f;
    float w1 = g.z - g.x, h1 = g.w - g.y;
    float w2 = p.z - p.x, h2 = p.w - p.y;
    float iw = fmaxf(fminf(g.z, p.z) - fmaxf(g.x, p.x), 0.0f);
    float ih = fmaxf(fminf(g.w, p.w) - fmaxf(g.y, p.y), 0.0f);
    float inter = iw * ih;
    float uni = w1 * h1 + w2 * h2 - inter + eps;
    float iou = inter / uni;
    float cw = fmaxf(g.z, p.z) - fminf(g.x, p.x);
    float ch = fmaxf(g.w, p.w) - fminf(g.y, p.y);
    float c2 = cw * cw + ch * ch + eps;
    float dx = p.x + p.z - g.x - g.z;
    float dy = p.y + p.w - g.y - g.w;
    float rho2 = (dx * dx + dy * dy) * 0.25f;
    float d = atanf(w1 / (h1 + eps)) - atanf(w2 / (h2 + eps));
    float v = 0.4052847345693511f * d * d;   // 4/pi^2
    float alpha = v / (v - iou + 1.0f + eps);
    return iou - (rho2 / c2 + v * alpha);
}

static __device__ __forceinline__ bool inside_box(float2 a, float4 g) {
    float m0 = fminf(a.x - g.x, a.y - g.y);
    float m1 = fminf(g.z - a.x, g.w - a.y);
    return fminf(m0, m1) > EPS9;
}

// ---------------- K0: init scratch ----------------
__global__ void k_init() {
    int i = blockIdx.x * blockDim.x + threadIdx.x;
    if (i < BSZ * NA) g_cnt[i] = 0;
    if (i < BSZ * NM) { g_pos_al[i] = 0u; g_pos_ov[i] = 0u; }
}

// ---------------- K1: per (b,m) top-10 of align, record selections --------
// Per-thread top-10 of POSITIVE aligns kept strictly in registers (no local
// memory). Zero-valued entries (lax.top_k index-ascending tie semantics) are
// reconstructed after the merge: if merged positives P<10, they are ALL the
// positives for this gt, so the remaining slots are the smallest anchor
// indices not in the positive set.
__global__ void __launch_bounds__(THREADS) k_phaseA(
    const float* __restrict__ pd_scores, const float* __restrict__ pd_bboxes,
    const float* __restrict__ anc, const int* __restrict__ gt_labels,
    const float* __restrict__ gt_bboxes)
{
    int bm = blockIdx.x;
    int b = bm / NM;
    int tid = threadIdx.x;

    float4 g = __ldg((const float4*)(gt_bboxes) + bm);
    int lbl = __ldg(gt_labels + bm);
    const float* sc = pd_scores + (size_t)b * NA * NC + lbl;
    const float4* pb = (const float4*)pd_bboxes + (size_t)b * NA;
    const float2* ap = (const float2*)anc;

    // register-resident sorted top-10 of positives (value desc, index asc)
    float tv[KTOP]; int ti[KTOP];
#pragma unroll
    for (int k = 0; k < KTOP; k++) { tv[k] = 0.0f; ti[k] = 0x7fffffff; }

    for (int a = tid; a < NA; a += THREADS) {
        float2 an = __ldg(ap + a);
        if (!inside_box(an, g)) continue;
        float4 p = __ldg(pb + a);
        float ov = fmaxf(ciou_f(g, p), 0.0f);
        if (ov <= 0.0f) continue;
        float s = __ldg(sc + (size_t)a * NC);
        float o2 = ov * ov;
        float v = sqrtf(s) * o2 * o2 * o2;
        // strict >: equal values keep the earlier (smaller) index
        if (v > tv[KTOP - 1]) {
            tv[KTOP - 1] = v; ti[KTOP - 1] = a;
#pragma unroll
            for (int k = KTOP - 1; k > 0; k--) {
                if (tv[k] > tv[k - 1]) {
                    float fv = tv[k]; tv[k] = tv[k - 1]; tv[k - 1] = fv;
                    int  iv = ti[k]; ti[k] = ti[k - 1]; ti[k - 1] = iv;
                }
            }
        }
    }

    __shared__ float sv[THREADS * KTOP];
    __shared__ int   si[THREADS * KTOP];
#pragma unroll
    for (int k = 0; k < KTOP; k++) { sv[tid * KTOP + k] = tv[k]; si[tid * KTOP + k] = ti[k]; }

    for (int off = THREADS / 2; off > 0; off >>= 1) {
        __syncthreads();
        if (tid < off) {
            float* va = &sv[tid * KTOP];          int* ia = &si[tid * KTOP];
            float* vb = &sv[(tid + off) * KTOP];  int* ib = &si[(tid + off) * KTOP];
            float mv[KTOP]; int mi[KTOP];
            int x = 0, y = 0;
#pragma unroll
            for (int k = 0; k < KTOP; k++) {
                bool tA = (va[x] > vb[y]) || (va[x] == vb[y] && ia[x] < ib[y]);
                if (tA) { mv[k] = va[x]; mi[k] = ia[x]; x++; }
                else    { mv[k] = vb[y]; mi[k] = ib[y]; y++; }
            }
#pragma unroll
            for (int k = 0; k < KTOP; k++) { va[k] = mv[k]; ia[k] = mi[k]; }
        }
    }
    __syncthreads();

    // zero-fill: if fewer than 10 positives, remaining topk slots are the
    // globally smallest anchor indices with align==0 (i.e., not positive).
    if (tid == 0) {
        int P = 0;
        while (P < KTOP && sv[P] > 0.0f) P++;
        int a = 0;
        for (int slot = P; slot < KTOP; ) {
            bool isPos = false;
            for (int j = 0; j < P; j++) isPos |= (si[j] == a);
            if (!isPos) { si[slot] = a; sv[slot] = 0.0f; slot++; }
            a++;
        }
    }
    __syncthreads();

    // top-10 winners: count only those inside the gt (mask_pos = topk & in_gts)
    if (tid < KTOP) {
        int a = si[tid];
        float al = sv[tid];
        float2 an = __ldg(ap + a);
        if (inside_box(an, g)) {
            size_t i = (size_t)b * NA + a;
            atomicAdd(&g_cnt[i], 1);
            g_m[i] = bm % NM;
            float4 p = __ldg(pb + a);
            float ov = fmaxf(ciou_f(g, p), 0.0f);
            g_al[i] = al;
            g_ov[i] = ov;
        }
    }
}

// ---------------- K2: resolve per-anchor assignment, write 4 outputs ------
__global__ void __launch_bounds__(THREADS) k_phaseB(
    const float* __restrict__ pd_scores, const float* __restrict__ pd_bboxes,
    const float* __restrict__ anc, const int* __restrict__ gt_labels,
    const float* __restrict__ gt_bboxes, float* __restrict__ out)
{
    int b = blockIdx.y;
    __shared__ float4 sg[NM];
    __shared__ int sl[NM];
    int tid = threadIdx.x;
    if (tid < NM) {
        sg[tid] = ((const float4*)gt_bboxes)[b * NM + tid];
        sl[tid] = gt_labels[b * NM + tid];
    }
    __syncthreads();

    int a = blockIdx.x * THREADS + tid;
    if (a >= NA) return;
    size_t i = (size_t)b * NA + a;

    int cnt = g_cnt[i];
    int tgt = 0; float al = 0.0f, ov = 0.0f; int fg = 0;

    if (cnt == 1) {
        tgt = g_m[i]; al = g_al[i]; ov = g_ov[i]; fg = 1;
    } else if (cnt > 1) {
        // multi-assigned: argmax over m of overlaps (ties -> lowest m)
        float2 an = ((const float2*)anc)[a];
        float4 p = ((const float4*)pd_bboxes)[(size_t)b * NA + a];
        float best = -1.0f; int bm = 0;
#pragma unroll 4
        for (int m = 0; m < NM; m++) {
            float4 g = sg[m];
            float ovm = inside_box(an, g) ? fmaxf(ciou_f(g, p), 0.0f) : 0.0f;
            if (ovm > best) { best = ovm; bm = m; }
        }
        tgt = bm; ov = best; fg = 1;
        float4 g = sg[tgt];
        if (inside_box(an, g) && ov > 0.0f) {
            float s = pd_scores[(size_t)b * NA * NC + (size_t)a * NC + sl[tgt]];
            float o2 = ov * ov;
            al = sqrtf(s) * o2 * o2 * o2;
        } else {
            al = 0.0f;
        }
    }

    g_tgt[i] = tgt; g_fg[i] = fg; g_fin[i] = al;
    if (fg) {
        atomicMax(&g_pos_al[b * NM + tgt], __float_as_uint(al));
        atomicMax(&g_pos_ov[b * NM + tgt], __float_as_uint(ov));
    }

    // outputs: [labels | bboxes | scores | fg | gt_idx], all float32
    const size_t N = (size_t)BSZ * NA;
    float* out_lab = out;
    float* out_box = out + N;
    float* out_fg  = out + N * (size_t)(1 + 4 + NC);
    float* out_idx = out_fg + N;

    out_lab[i] = fg ? (float)sl[tgt] : (float)NC;
    ((float4*)out_box)[i] = sg[tgt];
    out_fg[i]  = fg ? 1.0f : 0.0f;
    out_idx[i] = (float)tgt;
}

// ---------------- K3: norm + one-hot target_scores (coalesced writes) -----
#define APB 64   // anchors per block
__global__ void __launch_bounds__(THREADS) k_phaseD(
    const int* __restrict__ gt_labels, float* __restrict__ out)
{
    int b = blockIdx.y;
    int a0 = blockIdx.x * APB;
    int tid = threadIdx.x;

    __shared__ float s_norm[APB];
    __shared__ int   s_lbl[APB];

    if (tid < APB) {
        int a = a0 + tid;
        float norm = 0.0f; int lbl = -1;
        if (a < NA) {
            size_t i = (size_t)b * NA + a;
            if (g_fg[i]) {
                int t = g_tgt[i];
                lbl = gt_labels[b * NM + t];
                float pa = __uint_as_float(g_pos_al[b * NM + t]);
                float po = __uint_as_float(g_pos_ov[b * NM + t]);
                norm = g_fin[i] * po / (pa + EPS9);
            }
        }
        s_norm[tid] = norm; s_lbl[tid] = lbl;
    }
    __syncthreads();

    // block writes APB*NC floats = APB*20 float4, contiguous & coalesced
    float4* base = (float4*)(out + (size_t)BSZ * NA * 5) +
                   ((size_t)b * NA + a0) * (NC / 4);
#pragma unroll
    for (int r = 0; r < (APB * NC / 4) / THREADS; r++) {
        int idx = r * THREADS + tid;            // 0 .. 1279
        int al  = idx / (NC / 4);               // local anchor
        int k   = idx - al * (NC / 4);          // float4 slot within row
        if (a0 + al < NA) {
            int lbl = s_lbl[al];
            float4 w = make_float4(0.f, 0.f, 0.f, 0.f);
            if ((lbl >> 2) == k) {
                float n = s_norm[al];
                int l4 = lbl & 3;
                if      (l4 == 0) w.x = n;
                else if (l4 == 1) w.y = n;
                else if (l4 == 2) w.z = n;
                else              w.w = n;
            }
            base[idx] = w;
        }
    }
}

// ---------------- launcher ----------------
extern "C" void kernel_launch(void* const* d_in, const int* in_sizes, int n_in,
                              void* d_out, int out_size)
{
    const float* pd_scores = (const float*)d_in[0];   // (16,8400,80) f32
    const float* pd_bboxes = (const float*)d_in[1];   // (16,8400,4)  f32
    const float* anc       = (const float*)d_in[2];   // (8400,2)     f32
    const int*   gt_labels = (const int*)  d_in[3];   // (16,64,1)    i32
    const float* gt_bboxes = (const float*)d_in[4];   // (16,64,4)    f32
    // d_in[5] = mask_gt (all true) -> ignored
    float* out = (float*)d_out;

    (void)in_sizes; (void)n_in; (void)out_size;

    dim3 gInit((BSZ * NA + THREADS - 1) / THREADS);
    k_init<<<gInit, THREADS>>>();

    k_phaseA<<<BSZ * NM, THREADS>>>(pd_scores, pd_bboxes, anc, gt_labels, gt_bboxes);

    dim3 gBA((NA + THREADS - 1) / THREADS, BSZ);
    k_phaseB<<<gBA, THREADS>>>(pd_scores, pd_bboxes, anc, gt_labels, gt_bboxes, out);

    dim3 gD((NA + APB - 1) / APB, BSZ);
    k_phaseD<<<gD, THREADS>>>(gt_labels, out);
}

// round 6
// speedup vs baseline: 2.3971x; 1.2845x over previous
#include <cuda_runtime.h>
#include <math.h>
#include <stdint.h>

#define BSZ 16
#define NA  8400
#define NM  64
#define NC  80
#define KTOP 10
#define EPS9 1e-9f

#define NBX   16
#define NBINS 256          // 16x16 bins of 40px over 640x640
#define INV_BINW 0.025f    // 1/40
#define MAXC  1024         // max candidates per gt (worst ~450)

// ---------------- scratch (__device__ globals; allowed) ----------------
__device__ int      g_cnt[BSZ * NA];
__device__ int      g_m[BSZ * NA];
__device__ float    g_al[BSZ * NA];
__device__ float    g_ov[BSZ * NA];
__device__ int      g_tgt[BSZ * NA];
__device__ int      g_fg[BSZ * NA];
__device__ float    g_fin[BSZ * NA];
__device__ unsigned g_pos_al[BSZ * NM];
__device__ unsigned g_pos_ov[BSZ * NM];
// binning
__device__ float2   g_bxy[NA];
__device__ int      g_bidx[NA];
__device__ int      g_bs[NBINS + 1];

// ---------------- helpers ----------------
static __device__ __forceinline__ float ciou_f(float4 g, float4 p) {
    const float eps = 1e-7f;
    float w1 = g.z - g.x, h1 = g.w - g.y;
    float w2 = p.z - p.x, h2 = p.w - p.y;
    float iw = fmaxf(fminf(g.z, p.z) - fmaxf(g.x, p.x), 0.0f);
    float ih = fmaxf(fminf(g.w, p.w) - fmaxf(g.y, p.y), 0.0f);
    float inter = iw * ih;
    float uni = w1 * h1 + w2 * h2 - inter + eps;
    float iou = inter / uni;
    float cw = fmaxf(g.z, p.z) - fminf(g.x, p.x);
    float ch = fmaxf(g.w, p.w) - fminf(g.y, p.y);
    float c2 = cw * cw + ch * ch + eps;
    float dx = p.x + p.z - g.x - g.z;
    float dy = p.y + p.w - g.y - g.w;
    float rho2 = (dx * dx + dy * dy) * 0.25f;
    float d = atanf(w1 / (h1 + eps)) - atanf(w2 / (h2 + eps));
    float v = 0.4052847345693511f * d * d;   // 4/pi^2
    float alpha = v / (v - iou + 1.0f + eps);
    return iou - (rho2 / c2 + v * alpha);
}

static __device__ __forceinline__ bool inside_box(float2 a, float4 g) {
    float m0 = fminf(a.x - g.x, a.y - g.y);
    float m1 = fminf(g.z - a.x, g.w - a.y);
    return fminf(m0, m1) > EPS9;
}

static __device__ __forceinline__ unsigned long long u64max(
    unsigned long long a, unsigned long long b) { return a > b ? a : b; }

// ---------------- K0: zero scores region + init scratch -------------------
// scores region = BSZ*NA*NC floats = 2,688,000 float4. 8 f4 per thread.
__global__ void __launch_bounds__(256) k_zeroinit(float* __restrict__ out) {
    const float4 z = make_float4(0.f, 0.f, 0.f, 0.f);
    float4* sc = (float4*)(out + (size_t)BSZ * NA * 5);
    size_t base = (size_t)blockIdx.x * 2048 + threadIdx.x;
    const size_t nf4 = (size_t)BSZ * NA * NC / 4;
#pragma unroll
    for (int r = 0; r < 8; r++) {
        size_t j = base + (size_t)r * 256;
        if (j < nf4) sc[j] = z;
    }
    int t = blockIdx.x * 256 + threadIdx.x;
    if (t < BSZ * NA) g_cnt[t] = 0;
    if (t < BSZ * NM) { g_pos_al[t] = 0u; g_pos_ov[t] = 0u; }
}

// ---------------- K1: bin anchors into 16x16 grid (single block) ----------
__global__ void __launch_bounds__(256) k_bin(const float* __restrict__ anc) {
    __shared__ int cnt[NBINS];
    __shared__ int ofs[NBINS];
    int tid = threadIdx.x;
    if (tid < NBINS) cnt[tid] = 0;
    __syncthreads();
    for (int a = tid; a < NA; a += 256) {
        float2 an = ((const float2*)anc)[a];
        int bx = min(max((int)(an.x * INV_BINW), 0), NBX - 1);
        int by = min(max((int)(an.y * INV_BINW), 0), NBX - 1);
        atomicAdd(&cnt[by * NBX + bx], 1);
    }
    __syncthreads();
    if (tid == 0) {
        int s = 0;
        for (int i = 0; i < NBINS; i++) { ofs[i] = s; g_bs[i] = s; s += cnt[i]; }
        g_bs[NBINS] = s;
    }
    __syncthreads();
    for (int a = tid; a < NA; a += 256) {
        float2 an = ((const float2*)anc)[a];
        int bx = min(max((int)(an.x * INV_BINW), 0), NBX - 1);
        int by = min(max((int)(an.y * INV_BINW), 0), NBX - 1);
        int p = atomicAdd(&ofs[by * NBX + bx], 1);
        g_bxy[p] = an;
        g_bidx[p] = a;
    }
}

// ---------------- K2: per (b,m): binned scan + top-10 selection -----------
__global__ void __launch_bounds__(128) k_phaseA(
    const float* __restrict__ pd_scores, const float* __restrict__ pd_bboxes,
    const float* __restrict__ anc, const int* __restrict__ gt_labels,
    const float* __restrict__ gt_bboxes)
{
    int bm = blockIdx.x;
    int b = bm >> 6;
    int tid = threadIdx.x;

    __shared__ unsigned long long s_key[MAXC];  // (vbits<<32)|(0x7FFFFFFF - idx)
    __shared__ float s_ovs[MAXC];
    __shared__ int   s_ia[MAXC];
    __shared__ int   s_n, s_pos;
    if (tid == 0) s_n = 0;

    float4 g = __ldg((const float4*)gt_bboxes + bm);
    int lbl = __ldg(gt_labels + bm);
    const float* sc = pd_scores + (size_t)b * NA * NC + lbl;
    const float4* pb = (const float4*)pd_bboxes + (size_t)b * NA;
    __syncthreads();

    // bin rect covering all anchors strictly inside the box
    int bx0 = min(max((int)(g.x * INV_BINW), 0), NBX - 1);
    int bx1 = min(max((int)(g.z * INV_BINW), 0), NBX - 1);
    int by0 = min(max((int)(g.y * INV_BINW), 0), NBX - 1);
    int by1 = min(max((int)(g.w * INV_BINW), 0), NBX - 1);

    for (int by = by0; by <= by1; by++) {
        int j0 = g_bs[by * NBX + bx0];
        int j1 = g_bs[by * NBX + bx1 + 1];
        for (int j = j0 + tid; j < j1; j += 128) {
            float2 an = g_bxy[j];
            if (!inside_box(an, g)) continue;
            int a = g_bidx[j];
            float4 p = __ldg(pb + a);
            float ov = fmaxf(ciou_f(g, p), 0.0f);
            if (ov <= 0.0f) continue;
            float s = __ldg(sc + (size_t)a * NC);
            float o2 = ov * ov;
            float v = sqrtf(s) * o2 * o2 * o2;   // >0
            int pos = atomicAdd(&s_n, 1);
            if (pos < MAXC) {
                s_key[pos] = ((unsigned long long)__float_as_uint(v) << 32) |
                             (unsigned)(0x7FFFFFFF - a);
                s_ovs[pos] = ov;
                s_ia[pos]  = a;
            }
        }
    }
    __syncthreads();

    if (tid < 32) {
        int n = min(s_n, MAXC);
        int filled = 0;
#pragma unroll 1
        for (int k = 0; k < KTOP; k++) {
            unsigned long long best = 0ULL;
            for (int j = tid; j < n; j += 32) best = u64max(best, s_key[j]);
#pragma unroll
            for (int o = 16; o > 0; o >>= 1)
                best = u64max(best, __shfl_down_sync(0xffffffffu, best, o));
            best = __shfl_sync(0xffffffffu, best, 0);
            if (best == 0ULL) break;   // positives exhausted
            for (int j = tid; j < n; j += 32)
                if (s_key[j] == best) { s_key[j] = 0ULL; s_pos = j; }
            __syncwarp();
            if (tid == 0) {
                int a = 0x7FFFFFFF - (int)(best & 0x7FFFFFFFULL);
                float v = __uint_as_float((unsigned)(best >> 32));
                size_t i = (size_t)b * NA + a;
                atomicAdd(&g_cnt[i], 1);
                g_m[i]  = bm & 63;
                g_al[i] = v;
                g_ov[i] = s_ovs[s_pos];
            }
            __syncwarp();
            filled++;
        }
        // fillers: smallest global anchor indices not in the positive set
        // (only reachable when n < KTOP, so the positive set == all n entries)
        if (tid == 0 && filled < KTOP) {
            int a = 0;
            for (int slot = filled; slot < KTOP; ) {
                bool isPos = false;
                for (int j = 0; j < n; j++) if (s_ia[j] == a) { isPos = true; break; }
                if (!isPos) {
                    float2 an = ((const float2*)anc)[a];
                    if (inside_box(an, g)) {
                        size_t i = (size_t)b * NA + a;
                        atomicAdd(&g_cnt[i], 1);
                        g_m[i]  = bm & 63;
                        g_al[i] = 0.0f;
                        float4 p = __ldg(pb + a);
                        g_ov[i] = fmaxf(ciou_f(g, p), 0.0f);
                    }
                    slot++;
                }
                a++;
            }
        }
    }
}

// ---------------- K3: resolve per-anchor assignment, write 4 outputs ------
__global__ void __launch_bounds__(256) k_phaseB(
    const float* __restrict__ pd_scores, const float* __restrict__ pd_bboxes,
    const float* __restrict__ anc, const int* __restrict__ gt_labels,
    const float* __restrict__ gt_bboxes, float* __restrict__ out)
{
    int b = blockIdx.y;
    __shared__ float4 sg[NM];
    __shared__ int sl[NM];
    int tid = threadIdx.x;
    if (tid < NM) {
        sg[tid] = ((const float4*)gt_bboxes)[b * NM + tid];
        sl[tid] = gt_labels[b * NM + tid];
    }
    __syncthreads();

    int a = blockIdx.x * 256 + tid;
    if (a >= NA) return;
    size_t i = (size_t)b * NA + a;

    int cnt = g_cnt[i];
    int tgt = 0; float al = 0.0f, ov = 0.0f; int fg = 0;

    if (cnt == 1) {
        tgt = g_m[i]; al = g_al[i]; ov = g_ov[i]; fg = 1;
    } else if (cnt > 1) {
        float2 an = ((const float2*)anc)[a];
        float4 p = ((const float4*)pd_bboxes)[(size_t)b * NA + a];
        float best = -1.0f; int bmx = 0;
#pragma unroll 4
        for (int m = 0; m < NM; m++) {
            float4 gg = sg[m];
            float ovm = inside_box(an, gg) ? fmaxf(ciou_f(gg, p), 0.0f) : 0.0f;
            if (ovm > best) { best = ovm; bmx = m; }
        }
        tgt = bmx; ov = best; fg = 1;
        float4 gg = sg[tgt];
        if (inside_box(an, gg) && ov > 0.0f) {
            float s = pd_scores[(size_t)b * NA * NC + (size_t)a * NC + sl[tgt]];
            float o2 = ov * ov;
            al = sqrtf(s) * o2 * o2 * o2;
        } else {
            al = 0.0f;
        }
    }

    g_tgt[i] = tgt; g_fg[i] = fg; g_fin[i] = al;
    if (fg) {
        atomicMax(&g_pos_al[b * NM + tgt], __float_as_uint(al));
        atomicMax(&g_pos_ov[b * NM + tgt], __float_as_uint(ov));
    }

    const size_t N = (size_t)BSZ * NA;
    float* out_lab = out;
    float* out_box = out + N;
    float* out_fg  = out + N * (size_t)(1 + 4 + NC);
    float* out_idx = out_fg + N;

    out_lab[i] = fg ? (float)sl[tgt] : (float)NC;
    ((float4*)out_box)[i] = sg[tgt];
    out_fg[i]  = fg ? 1.0f : 0.0f;
    out_idx[i] = (float)tgt;
}

// ---------------- K4: scatter nonzero scores -------------------------------
__global__ void __launch_bounds__(256) k_scatter(
    const int* __restrict__ gt_labels, float* __restrict__ out)
{
    int b = blockIdx.y;
    int a = blockIdx.x * 256 + threadIdx.x;
    if (a >= NA) return;
    size_t i = (size_t)b * NA + a;
    if (!g_fg[i]) return;
    int t = g_tgt[i];
    int lbl = gt_labels[b * NM + t];
    float pa = __uint_as_float(g_pos_al[b * NM + t]);
    float po = __uint_as_float(g_pos_ov[b * NM + t]);
    float norm = g_fin[i] * po / (pa + EPS9);
    out[(size_t)BSZ * NA * 5 + i * (size_t)NC + lbl] = norm;
}

// ---------------- launcher ----------------
extern "C" void kernel_launch(void* const* d_in, const int* in_sizes, int n_in,
                              void* d_out, int out_size)
{
    const float* pd_scores = (const float*)d_in[0];
    const float* pd_bboxes = (const float*)d_in[1];
    const float* anc       = (const float*)d_in[2];
    const int*   gt_labels = (const int*)  d_in[3];
    const float* gt_bboxes = (const float*)d_in[4];
    float* out = (float*)d_out;

    (void)in_sizes; (void)n_in; (void)out_size;

    const size_t nf4 = (size_t)BSZ * NA * NC / 4;           // 2,688,000
    int gz = (int)((nf4 + 2047) / 2048);                    // 1313
    k_zeroinit<<<gz, 256>>>(out);

    k_bin<<<1, 256>>>(anc);

    k_phaseA<<<BSZ * NM, 128>>>(pd_scores, pd_bboxes, anc, gt_labels, gt_bboxes);

    dim3 gBA((NA + 255) / 256, BSZ);
    k_phaseB<<<gBA, 256>>>(pd_scores, pd_bboxes, anc, gt_labels, gt_bboxes, out);

    k_scatter<<<gBA, 256>>>(gt_labels, out);
}

// round 7
// speedup vs baseline: 2.5379x; 1.0588x over previous
#include <cuda_runtime.h>
#include <math.h>
#include <stdint.h>

#define BSZ 16
#define NA  8400
#define NM  64
#define NC  80
#define KTOP 10
#define EPS9 1e-9f

#define NBX   16
#define NBINS 256          // 16x16 bins of 40px over 640x640
#define INV_BINW 0.025f    // 1/40
#define MAXC  1024         // max candidates per gt (worst ~450)

#define ZBLK 1313          // blocks that zero the scores region

// ---------------- scratch (__device__ globals; allowed) ----------------
__device__ int      g_cnt[BSZ * NA];
__device__ int      g_m[BSZ * NA];
__device__ float    g_al[BSZ * NA];
__device__ float    g_ov[BSZ * NA];
__device__ int      g_tgt[BSZ * NA];
__device__ float    g_fin[BSZ * NA];
__device__ unsigned g_pos_al[BSZ * NM];
__device__ unsigned g_pos_ov[BSZ * NM];
// binning
__device__ float2   g_bxy[NA];
__device__ int      g_bidx[NA];
__device__ int      g_bs[NBINS + 1];

// ---------------- helpers ----------------
static __device__ __forceinline__ float ciou_f(float4 g, float4 p) {
    const float eps = 1e-7f;
    float w1 = g.z - g.x, h1 = g.w - g.y;
    float w2 = p.z - p.x, h2 = p.w - p.y;
    float iw = fmaxf(fminf(g.z, p.z) - fmaxf(g.x, p.x), 0.0f);
    float ih = fmaxf(fminf(g.w, p.w) - fmaxf(g.y, p.y), 0.0f);
    float inter = iw * ih;
    float uni = w1 * h1 + w2 * h2 - inter + eps;
    float iou = inter / uni;
    float cw = fmaxf(g.z, p.z) - fminf(g.x, p.x);
    float ch = fmaxf(g.w, p.w) - fminf(g.y, p.y);
    float c2 = cw * cw + ch * ch + eps;
    float dx = p.x + p.z - g.x - g.z;
    float dy = p.y + p.w - g.y - g.w;
    float rho2 = (dx * dx + dy * dy) * 0.25f;
    float d = atanf(w1 / (h1 + eps)) - atanf(w2 / (h2 + eps));
    float v = 0.4052847345693511f * d * d;   // 4/pi^2
    float alpha = v / (v - iou + 1.0f + eps);
    return iou - (rho2 / c2 + v * alpha);
}

static __device__ __forceinline__ bool inside_box(float2 a, float4 g) {
    float m0 = fminf(a.x - g.x, a.y - g.y);
    float m1 = fminf(g.z - a.x, g.w - a.y);
    return fminf(m0, m1) > EPS9;
}

static __device__ __forceinline__ unsigned long long u64max(
    unsigned long long a, unsigned long long b) { return a > b ? a : b; }

// ---------------- K0: zero scores + init scratch + bin anchors (fused) ----
// Blocks [0, ZBLK) zero the scores region and init scratch.
// Block ZBLK performs the anchor binning (parallel scan).
__global__ void __launch_bounds__(256) k_prep(float* __restrict__ out,
                                              const float* __restrict__ anc) {
    int tid = threadIdx.x;

    if (blockIdx.x == ZBLK) {
        // ---- binning block ----
        __shared__ int cnt[NBINS];
        __shared__ int ofs[NBINS];
        __shared__ int scn[NBINS];
        cnt[tid] = 0;
        __syncthreads();
        for (int a = tid; a < NA; a += 256) {
            float2 an = ((const float2*)anc)[a];
            int bx = min(max((int)(an.x * INV_BINW), 0), NBX - 1);
            int by = min(max((int)(an.y * INV_BINW), 0), NBX - 1);
            atomicAdd(&cnt[by * NBX + bx], 1);
        }
        __syncthreads();
        int x = cnt[tid];
        scn[tid] = x;
        __syncthreads();
#pragma unroll
        for (int d = 1; d < NBINS; d <<= 1) {
            int v = (tid >= d) ? scn[tid - d] : 0;
            __syncthreads();
            scn[tid] += v;
            __syncthreads();
        }
        int excl = scn[tid] - x;
        ofs[tid] = excl;
        g_bs[tid] = excl;
        if (tid == NBINS - 1) g_bs[NBINS] = scn[tid];
        __syncthreads();
        for (int a = tid; a < NA; a += 256) {
            float2 an = ((const float2*)anc)[a];
            int bx = min(max((int)(an.x * INV_BINW), 0), NBX - 1);
            int by = min(max((int)(an.y * INV_BINW), 0), NBX - 1);
            int p = atomicAdd(&ofs[by * NBX + bx], 1);
            g_bxy[p] = an;
            g_bidx[p] = a;
        }
        return;
    }

    // ---- zeroing blocks ----
    const float4 z = make_float4(0.f, 0.f, 0.f, 0.f);
    float4* sc = (float4*)(out + (size_t)BSZ * NA * 5);
    size_t base = (size_t)blockIdx.x * 2048 + tid;
    const size_t nf4 = (size_t)BSZ * NA * NC / 4;
#pragma unroll
    for (int r = 0; r < 8; r++) {
        size_t j = base + (size_t)r * 256;
        if (j < nf4) sc[j] = z;
    }
    int t = blockIdx.x * 256 + tid;
    if (t < BSZ * NA) g_cnt[t] = 0;
    if (t < BSZ * NM) { g_pos_al[t] = 0u; g_pos_ov[t] = 0u; }
}

// ---------------- K1: per (b,m): binned scan + top-10 selection -----------
__global__ void __launch_bounds__(128) k_phaseA(
    const float* __restrict__ pd_scores, const float* __restrict__ pd_bboxes,
    const float* __restrict__ anc, const int* __restrict__ gt_labels,
    const float* __restrict__ gt_bboxes)
{
    int bm = blockIdx.x;
    int b = bm >> 6;
    int tid = threadIdx.x;

    __shared__ unsigned long long s_key[MAXC];  // (vbits<<32)|(0x7FFFFFFF - idx)
    __shared__ float s_ovs[MAXC];
    __shared__ int   s_ia[MAXC];
    __shared__ int   s_n, s_pos;
    if (tid == 0) s_n = 0;

    float4 g = __ldg((const float4*)gt_bboxes + bm);
    int lbl = __ldg(gt_labels + bm);
    const float* sc = pd_scores + (size_t)b * NA * NC + lbl;
    const float4* pb = (const float4*)pd_bboxes + (size_t)b * NA;
    __syncthreads();

    int bx0 = min(max((int)(g.x * INV_BINW), 0), NBX - 1);
    int bx1 = min(max((int)(g.z * INV_BINW), 0), NBX - 1);
    int by0 = min(max((int)(g.y * INV_BINW), 0), NBX - 1);
    int by1 = min(max((int)(g.w * INV_BINW), 0), NBX - 1);

    for (int by = by0; by <= by1; by++) {
        int j0 = g_bs[by * NBX + bx0];
        int j1 = g_bs[by * NBX + bx1 + 1];
        for (int j = j0 + tid; j < j1; j += 128) {
            float2 an = g_bxy[j];
            if (!inside_box(an, g)) continue;
            int a = g_bidx[j];
            float4 p = __ldg(pb + a);
            float ov = fmaxf(ciou_f(g, p), 0.0f);
            if (ov <= 0.0f) continue;
            float s = __ldg(sc + (size_t)a * NC);
            float o2 = ov * ov;
            float v = sqrtf(s) * o2 * o2 * o2;   // >0
            int pos = atomicAdd(&s_n, 1);
            if (pos < MAXC) {
                s_key[pos] = ((unsigned long long)__float_as_uint(v) << 32) |
                             (unsigned)(0x7FFFFFFF - a);
                s_ovs[pos] = ov;
                s_ia[pos]  = a;
            }
        }
    }
    __syncthreads();

    if (tid < 32) {
        int n = min(s_n, MAXC);
        int filled = 0;
#pragma unroll 1
        for (int k = 0; k < KTOP; k++) {
            unsigned long long best = 0ULL;
            for (int j = tid; j < n; j += 32) best = u64max(best, s_key[j]);
#pragma unroll
            for (int o = 16; o > 0; o >>= 1)
                best = u64max(best, __shfl_down_sync(0xffffffffu, best, o));
            best = __shfl_sync(0xffffffffu, best, 0);
            if (best == 0ULL) break;   // positives exhausted
            for (int j = tid; j < n; j += 32)
                if (s_key[j] == best) { s_key[j] = 0ULL; s_pos = j; }
            __syncwarp();
            if (tid == 0) {
                int a = 0x7FFFFFFF - (int)(best & 0x7FFFFFFFULL);
                float v = __uint_as_float((unsigned)(best >> 32));
                size_t i = (size_t)b * NA + a;
                atomicAdd(&g_cnt[i], 1);
                g_m[i]  = bm & 63;
                g_al[i] = v;
                g_ov[i] = s_ovs[s_pos];
            }
            __syncwarp();
            filled++;
        }
        // fillers: smallest global anchor indices not in the positive set
        if (tid == 0 && filled < KTOP) {
            int a = 0;
            for (int slot = filled; slot < KTOP; ) {
                bool isPos = false;
                for (int j = 0; j < n; j++) if (s_ia[j] == a) { isPos = true; break; }
                if (!isPos) {
                    float2 an = ((const float2*)anc)[a];
                    if (inside_box(an, g)) {
                        size_t i = (size_t)b * NA + a;
                        atomicAdd(&g_cnt[i], 1);
                        g_m[i]  = bm & 63;
                        g_al[i] = 0.0f;
                        float4 p = __ldg(pb + a);
                        g_ov[i] = fmaxf(ciou_f(g, p), 0.0f);
                    }
                    slot++;
                }
                a++;
            }
        }
    }
}

// ---------------- K2: resolve assignment + pos-max atomics ----------------
__global__ void __launch_bounds__(256) k_phaseB(
    const float* __restrict__ pd_scores, const float* __restrict__ pd_bboxes,
    const float* __restrict__ anc, const int* __restrict__ gt_labels,
    const float* __restrict__ gt_bboxes)
{
    int b = blockIdx.y;
    int a = blockIdx.x * 256 + threadIdx.x;
    if (a >= NA) return;
    size_t i = (size_t)b * NA + a;

    // independent upfront loads (no dependent chain)
    int   cnt = __ldg(&g_cnt[i]);
    int   tgt = __ldg(&g_m[i]);
    float al  = __ldg(&g_al[i]);
    float ov  = __ldg(&g_ov[i]);

    if (cnt == 0) { g_tgt[i] = 0; g_fin[i] = 0.0f; return; }

    if (cnt > 1) {
        // multi-assigned: argmax over m of overlaps (ties -> lowest m)
        float2 an = __ldg((const float2*)anc + a);
        float4 p  = __ldg((const float4*)pd_bboxes + (size_t)b * NA + a);
        const float4* gb = (const float4*)gt_bboxes + b * NM;
        float best = -1.0f; int bmx = 0;
#pragma unroll 4
        for (int m = 0; m < NM; m++) {
            float4 gg = __ldg(gb + m);
            float ovm = inside_box(an, gg) ? fmaxf(ciou_f(gg, p), 0.0f) : 0.0f;
            if (ovm > best) { best = ovm; bmx = m; }
        }
        tgt = bmx; ov = best;
        float4 gg = __ldg(gb + tgt);
        if (inside_box(an, gg) && ov > 0.0f) {
            int lbl = __ldg(gt_labels + b * NM + tgt);
            float s = pd_scores[(size_t)b * NA * NC + (size_t)a * NC + lbl];
            float o2 = ov * ov;
            al = sqrtf(s) * o2 * o2 * o2;
        } else {
            al = 0.0f;
        }
    }

    g_tgt[i] = tgt;
    g_fin[i] = al;
    atomicMax(&g_pos_al[b * NM + tgt], __float_as_uint(al));
    atomicMax(&g_pos_ov[b * NM + tgt], __float_as_uint(ov));
}

// ---------------- K3: write all outputs -----------------------------------
__global__ void __launch_bounds__(256) k_phaseC(
    const int* __restrict__ gt_labels, const float* __restrict__ gt_bboxes,
    float* __restrict__ out)
{
    int b = blockIdx.y;
    int a = blockIdx.x * 256 + threadIdx.x;
    if (a >= NA) return;
    size_t i = (size_t)b * NA + a;

    int   cnt = __ldg(&g_cnt[i]);
    int   tgt = __ldg(&g_tgt[i]);
    float fin = __ldg(&g_fin[i]);
    int fg = cnt > 0;

    int lbl = __ldg(gt_labels + b * NM + tgt);
    float4 box = __ldg((const float4*)gt_bboxes + b * NM + tgt);

    const size_t N = (size_t)BSZ * NA;
    out[i] = fg ? (float)lbl : (float)NC;                 // labels
    ((float4*)(out + N))[i] = box;                        // bboxes
    out[N * (size_t)(1 + 4 + NC) + i] = fg ? 1.0f : 0.0f; // fg
    out[N * (size_t)(2 + 4 + NC) + i] = (float)tgt;       // gt_idx

    if (fg) {
        float pa = __uint_as_float(__ldg(&g_pos_al[b * NM + tgt]));
        float po = __uint_as_float(__ldg(&g_pos_ov[b * NM + tgt]));
        float norm = fin * po / (pa + EPS9);
        out[N * 5 + i * (size_t)NC + lbl] = norm;         // sparse score
    }
}

// ---------------- launcher ----------------
extern "C" void kernel_launch(void* const* d_in, const int* in_sizes, int n_in,
                              void* d_out, int out_size)
{
    const float* pd_scores = (const float*)d_in[0];
    const float* pd_bboxes = (const float*)d_in[1];
    const float* anc       = (const float*)d_in[2];
    const int*   gt_labels = (const int*)  d_in[3];
    const float* gt_bboxes = (const float*)d_in[4];
    float* out = (float*)d_out;

    (void)in_sizes; (void)n_in; (void)out_size;

    k_prep<<<ZBLK + 1, 256>>>(out, anc);

    k_phaseA<<<BSZ * NM, 128>>>(pd_scores, pd_bboxes, anc, gt_labels, gt_bboxes);

    dim3 gBA((NA + 255) / 256, BSZ);
    k_phaseB<<<gBA, 256>>>(pd_scores, pd_bboxes, anc, gt_labels, gt_bboxes);

    k_phaseC<<<gBA, 256>>>(gt_labels, gt_bboxes, out);
}

// round 8
// speedup vs baseline: 2.7446x; 1.0814x over previous
#include <cuda_runtime.h>
#include <math.h>
#include <stdint.h>

#define BSZ 16
#define NA  8400
#define NM  64
#define NC  80
#define KTOP 10
#define EPS9 1e-9f

#define NBX   16
#define NBINS 256          // 16x16 bins of 40px over 640x640
#define INV_BINW 0.025f    // 1/40
#define MAXC  1024         // max candidates per gt (worst ~450)

#define ZBLK 525           // blocks that init scratch (g_cnt etc.)

// ---------------- scratch (__device__ globals; allowed) ----------------
__device__ int      g_cnt[BSZ * NA];
__device__ int      g_m[BSZ * NA];
__device__ float    g_al[BSZ * NA];
__device__ float    g_ov[BSZ * NA];
__device__ int      g_lbl[BSZ * NA];     // final label, -1 = background
__device__ int      g_tgt[BSZ * NA];
__device__ float    g_fin[BSZ * NA];
__device__ unsigned g_pos_al[BSZ * NM];
__device__ unsigned g_pos_ov[BSZ * NM];
// binning
__device__ float2   g_bxy[NA];
__device__ int      g_bidx[NA];
__device__ int      g_bs[NBINS + 1];

// ---------------- helpers ----------------
static __device__ __forceinline__ float ciou_f(float4 g, float4 p) {
    const float eps = 1e-7f;
    float w1 = g.z - g.x, h1 = g.w - g.y;
    float w2 = p.z - p.x, h2 = p.w - p.y;
    float iw = fmaxf(fminf(g.z, p.z) - fmaxf(g.x, p.x), 0.0f);
    float ih = fmaxf(fminf(g.w, p.w) - fmaxf(g.y, p.y), 0.0f);
    float inter = iw * ih;
    float uni = w1 * h1 + w2 * h2 - inter + eps;
    float iou = inter / uni;
    float cw = fmaxf(g.z, p.z) - fminf(g.x, p.x);
    float ch = fmaxf(g.w, p.w) - fminf(g.y, p.y);
    float c2 = cw * cw + ch * ch + eps;
    float dx = p.x + p.z - g.x - g.z;
    float dy = p.y + p.w - g.y - g.w;
    float rho2 = (dx * dx + dy * dy) * 0.25f;
    float d = atanf(w1 / (h1 + eps)) - atanf(w2 / (h2 + eps));
    float v = 0.4052847345693511f * d * d;   // 4/pi^2
    float alpha = v / (v - iou + 1.0f + eps);
    return iou - (rho2 / c2 + v * alpha);
}

static __device__ __forceinline__ bool inside_box(float2 a, float4 g) {
    float m0 = fminf(a.x - g.x, a.y - g.y);
    float m1 = fminf(g.z - a.x, g.w - a.y);
    return fminf(m0, m1) > EPS9;
}

// ---------------- K0: init scratch + bin anchors (fused, small) -----------
__global__ void __launch_bounds__(256) k_prep(const float* __restrict__ anc) {
    int tid = threadIdx.x;

    if (blockIdx.x == ZBLK) {
        // ---- binning block ----
        __shared__ int cnt[NBINS];
        __shared__ int ofs[NBINS];
        __shared__ int scn[NBINS];
        cnt[tid] = 0;
        __syncthreads();
        for (int a = tid; a < NA; a += 256) {
            float2 an = ((const float2*)anc)[a];
            int bx = min(max((int)(an.x * INV_BINW), 0), NBX - 1);
            int by = min(max((int)(an.y * INV_BINW), 0), NBX - 1);
            atomicAdd(&cnt[by * NBX + bx], 1);
        }
        __syncthreads();
        int x = cnt[tid];
        scn[tid] = x;
        __syncthreads();
#pragma unroll
        for (int d = 1; d < NBINS; d <<= 1) {
            int v = (tid >= d) ? scn[tid - d] : 0;
            __syncthreads();
            scn[tid] += v;
            __syncthreads();
        }
        int excl = scn[tid] - x;
        ofs[tid] = excl;
        g_bs[tid] = excl;
        if (tid == NBINS - 1) g_bs[NBINS] = scn[tid];
        __syncthreads();
        for (int a = tid; a < NA; a += 256) {
            float2 an = ((const float2*)anc)[a];
            int bx = min(max((int)(an.x * INV_BINW), 0), NBX - 1);
            int by = min(max((int)(an.y * INV_BINW), 0), NBX - 1);
            int p = atomicAdd(&ofs[by * NBX + bx], 1);
            g_bxy[p] = an;
            g_bidx[p] = a;
        }
        return;
    }

    // ---- scratch init blocks ----
    int t = blockIdx.x * 256 + tid;
    if (t < BSZ * NA) g_cnt[t] = 0;
    if (t < BSZ * NM) { g_pos_al[t] = 0u; g_pos_ov[t] = 0u; }
}

// ---------------- K1: per (b,m) binned scan + parallel rank top-10 --------
__global__ void __launch_bounds__(128) k_phaseA(
    const float* __restrict__ pd_scores, const float* __restrict__ pd_bboxes,
    const float* __restrict__ anc, const int* __restrict__ gt_labels,
    const float* __restrict__ gt_bboxes)
{
    int bm = blockIdx.x;
    int b = bm >> 6;
    int tid = threadIdx.x;

    __shared__ unsigned long long s_key[MAXC];  // (vbits<<32)|(0x7FFFFFFF - idx)
    __shared__ float s_ovs[MAXC];
    __shared__ int   s_ia[MAXC];
    __shared__ int   s_n;
    if (tid == 0) s_n = 0;

    float4 g = __ldg((const float4*)gt_bboxes + bm);
    int lbl = __ldg(gt_labels + bm);
    const float* sc = pd_scores + (size_t)b * NA * NC + lbl;
    const float4* pb = (const float4*)pd_bboxes + (size_t)b * NA;
    __syncthreads();

    int bx0 = min(max((int)(g.x * INV_BINW), 0), NBX - 1);
    int bx1 = min(max((int)(g.z * INV_BINW), 0), NBX - 1);
    int by0 = min(max((int)(g.y * INV_BINW), 0), NBX - 1);
    int by1 = min(max((int)(g.w * INV_BINW), 0), NBX - 1);

    for (int by = by0; by <= by1; by++) {
        int j0 = g_bs[by * NBX + bx0];
        int j1 = g_bs[by * NBX + bx1 + 1];
        for (int j = j0 + tid; j < j1; j += 128) {
            float2 an = g_bxy[j];
            if (!inside_box(an, g)) continue;
            int a = g_bidx[j];
            float4 p = __ldg(pb + a);
            float ov = fmaxf(ciou_f(g, p), 0.0f);
            if (ov <= 0.0f) continue;
            float s = __ldg(sc + (size_t)a * NC);
            float o2 = ov * ov;
            float v = sqrtf(s) * o2 * o2 * o2;   // >0
            int pos = atomicAdd(&s_n, 1);
            if (pos < MAXC) {
                s_key[pos] = ((unsigned long long)__float_as_uint(v) << 32) |
                             (unsigned)(0x7FFFFFFF - a);
                s_ovs[pos] = ov;
                s_ia[pos]  = a;
            }
        }
    }
    __syncthreads();

    int n = min(s_n, MAXC);

    // parallel rank-select: keys are all distinct, winner iff rank < KTOP
    for (int c = tid; c < n; c += 128) {
        unsigned long long key = s_key[c];
        int rank = 0;
        for (int j = 0; j < n; j++) rank += (s_key[j] > key);
        if (rank < KTOP) {
            int a = s_ia[c];
            size_t i = (size_t)b * NA + a;
            atomicAdd(&g_cnt[i], 1);
            g_m[i]  = bm & 63;
            g_al[i] = __uint_as_float((unsigned)(key >> 32));
            g_ov[i] = s_ovs[c];
        }
    }

    // fillers when n < KTOP: the (KTOP-n) smallest global anchor indices not
    // in the positive set (all such indices are < n + KTOP <= 20 < 128).
    if (n < KTOP && tid < n + KTOP) {
        bool inPos = false; int less = 0;
        for (int j = 0; j < n; j++) {
            int ia = s_ia[j];
            inPos |= (ia == tid);
            less  += (ia < tid);
        }
        if (!inPos && (tid - less) < (KTOP - n)) {
            float2 an = __ldg((const float2*)anc + tid);
            if (inside_box(an, g)) {
                size_t i = (size_t)b * NA + tid;
                atomicAdd(&g_cnt[i], 1);
                g_m[i]  = bm & 63;
                g_al[i] = 0.0f;
                float4 p = __ldg(pb + tid);
                g_ov[i] = fmaxf(ciou_f(g, p), 0.0f);
            }
        }
    }
}

// ---------------- K2: resolve assignment + pos-max atomics ----------------
__global__ void __launch_bounds__(256) k_phaseB(
    const float* __restrict__ pd_scores, const float* __restrict__ pd_bboxes,
    const float* __restrict__ anc, const int* __restrict__ gt_labels,
    const float* __restrict__ gt_bboxes)
{
    int b = blockIdx.y;
    int a = blockIdx.x * 256 + threadIdx.x;
    if (a >= NA) return;
    size_t i = (size_t)b * NA + a;

    int   cnt = __ldg(&g_cnt[i]);
    int   tgt = __ldg(&g_m[i]);
    float al  = __ldg(&g_al[i]);
    float ov  = __ldg(&g_ov[i]);

    if (cnt == 0) { g_lbl[i] = -1; g_tgt[i] = 0; g_fin[i] = 0.0f; return; }

    if (cnt > 1) {
        // multi-assigned: argmax over m of overlaps (ties -> lowest m)
        float2 an = __ldg((const float2*)anc + a);
        float4 p  = __ldg((const float4*)pd_bboxes + (size_t)b * NA + a);
        const float4* gb = (const float4*)gt_bboxes + b * NM;
        float best = -1.0f; int bmx = 0;
#pragma unroll 4
        for (int m = 0; m < NM; m++) {
            float4 gg = __ldg(gb + m);
            float ovm = inside_box(an, gg) ? fmaxf(ciou_f(gg, p), 0.0f) : 0.0f;
            if (ovm > best) { best = ovm; bmx = m; }
        }
        tgt = bmx; ov = best;
        float4 gg = __ldg(gb + tgt);
        if (inside_box(an, gg) && ov > 0.0f) {
            int lb = __ldg(gt_labels + b * NM + tgt);
            float s = pd_scores[(size_t)b * NA * NC + (size_t)a * NC + lb];
            float o2 = ov * ov;
            al = sqrtf(s) * o2 * o2 * o2;
        } else {
            al = 0.0f;
        }
    }

    g_lbl[i] = __ldg(gt_labels + b * NM + tgt);
    g_tgt[i] = tgt;
    g_fin[i] = al;
    atomicMax(&g_pos_al[b * NM + tgt], __float_as_uint(al));
    atomicMax(&g_pos_ov[b * NM + tgt], __float_as_uint(ov));
}

// ---------------- K3: all outputs (dense coalesced score rows) ------------
#define APB 128
__global__ void __launch_bounds__(512) k_phaseC(
    const float* __restrict__ gt_bboxes, float* __restrict__ out)
{
    int b = blockIdx.y;
    int a0 = blockIdx.x * APB;
    int tid = threadIdx.x;

    __shared__ float s_norm[APB];
    __shared__ int   s_lbl[APB];

    const size_t N = (size_t)BSZ * NA;

    if (tid < APB) {
        int a = a0 + tid;
        float norm = 0.0f; int lbl = -1;
        if (a < NA) {
            size_t i = (size_t)b * NA + a;
            lbl     = __ldg(&g_lbl[i]);
            int tgt = __ldg(&g_tgt[i]);
            int fg  = lbl >= 0;

            float4 box = __ldg((const float4*)gt_bboxes + b * NM + tgt);
            out[i] = fg ? (float)lbl : (float)NC;            // labels
            ((float4*)(out + N))[i] = box;                   // bboxes
            out[N * (size_t)(1 + 4 + NC) + i] = fg ? 1.0f : 0.0f;  // fg
            out[N * (size_t)(2 + 4 + NC) + i] = (float)tgt;        // gt_idx

            if (fg) {
                float pa = __uint_as_float(__ldg(&g_pos_al[b * NM + tgt]));
                float po = __uint_as_float(__ldg(&g_pos_ov[b * NM + tgt]));
                norm = __ldg(&g_fin[i]) * po / (pa + EPS9);
            }
        }
        s_norm[tid] = norm; s_lbl[tid] = lbl;
    }
    __syncthreads();

    // dense score rows: APB*NC floats = APB*20 float4, coalesced
    float4* base = (float4*)(out + N * 5) + ((size_t)b * NA + a0) * (NC / 4);
#pragma unroll
    for (int r = 0; r < (APB * NC / 4) / 512; r++) {
        int idx = r * 512 + tid;                // 0 .. 2559
        int al  = idx / (NC / 4);               // local anchor
        int k   = idx - al * (NC / 4);          // float4 slot within row
        if (a0 + al < NA) {
            int lbl = s_lbl[al];
            float4 w = make_float4(0.f, 0.f, 0.f, 0.f);
            if ((lbl >> 2) == k) {
                float nv = s_norm[al];
                int l4 = lbl & 3;
                if      (l4 == 0) w.x = nv;
                else if (l4 == 1) w.y = nv;
                else if (l4 == 2) w.z = nv;
                else              w.w = nv;
            }
            base[idx] = w;
        }
    }
}

// ---------------- launcher ----------------
extern "C" void kernel_launch(void* const* d_in, const int* in_sizes, int n_in,
                              void* d_out, int out_size)
{
    const float* pd_scores = (const float*)d_in[0];
    const float* pd_bboxes = (const float*)d_in[1];
    const float* anc       = (const float*)d_in[2];
    const int*   gt_labels = (const int*)  d_in[3];
    const float* gt_bboxes = (const float*)d_in[4];
    float* out = (float*)d_out;

    (void)in_sizes; (void)n_in; (void)out_size;

    k_prep<<<ZBLK + 1, 256>>>(anc);

    k_phaseA<<<BSZ * NM, 128>>>(pd_scores, pd_bboxes, anc, gt_labels, gt_bboxes);

    dim3 gB((NA + 255) / 256, BSZ);
    k_phaseB<<<gB, 256>>>(pd_scores, pd_bboxes, anc, gt_labels, gt_bboxes);

    dim3 gC((NA + APB - 1) / APB, BSZ);
    k_phaseC<<<gC, 512>>>(gt_bboxes, out);
}